// round 9
// baseline (speedup 1.0000x reference)
#include <cuda_runtime.h>
#include <math.h>

// Problem constants (B,C,H,W,K) = (32,8,64,64,16)
#define BATCH 32
#define CHW    (8 * 64 * 64)           // 32768 elements per batch
#define N_ELEM (BATCH * CHW)           // 1,048,576
#define KMIX   16
#define TPB    128
#define TILE   128                     // elements per tile (== TPB)
#define NTILE  (N_ELEM / TILE)         // 8192 tiles
#define NSM    148
#define CTAS_PER_SM 4                  // smem-limited (2 x 24KB stages)
#define GRID   (NSM * CTAS_PER_SM)     // 592 persistent CTAs
#define F4_PER_TILE (TILE * KMIX / 4)  // 512 float4 per tensor per tile

__global__ void init_sldj_kernel(const float* __restrict__ sldj_in,
                                 float* __restrict__ sldj_out) {
    int i = threadIdx.x;
    if (i < BATCH) sldj_out[i] = sldj_in[i];
}

__device__ __forceinline__ void cp_async16(void* smem_dst, const void* gmem_src) {
    unsigned saddr = (unsigned)__cvta_generic_to_shared(smem_dst);
    asm volatile("cp.async.cg.shared.global [%0], [%1], 16;\n"
                 :: "r"(saddr), "l"(gmem_src));
}
__device__ __forceinline__ void cp_commit() {
    asm volatile("cp.async.commit_group;\n");
}
__device__ __forceinline__ void cp_wait1() {
    asm volatile("cp.async.wait_group 1;\n");
}
__device__ __forceinline__ void cp_wait0() {
    asm volatile("cp.async.wait_group 0;\n");
}

// smem: [stage][tensor][chunk] float4; layout identical to global (elem-major),
// so the prefetch is a flat, lane-contiguous copy (perfect coalescing).
__shared__ float4 sm_stage[2][3][F4_PER_TILE];   // 2*3*512*16 = 49152 B

__device__ __forceinline__ void prefetch_tile(int stage, int tile, int tid,
                                              const float4* __restrict__ pi4,
                                              const float4* __restrict__ mu4,
                                              const float4* __restrict__ s4) {
    const int base4 = tile * F4_PER_TILE;
#pragma unroll
    for (int c = 0; c < 4; c++) {
        const int chunk = c * TPB + tid;           // 0..511, lane-contiguous
        cp_async16(&sm_stage[stage][0][chunk], pi4 + base4 + chunk);
        cp_async16(&sm_stage[stage][1][chunk], mu4 + base4 + chunk);
        cp_async16(&sm_stage[stage][2][chunk], s4  + base4 + chunk);
    }
}

__global__ void __launch_bounds__(TPB)
coupling_kernel(const float*  __restrict__ x_change,
                const float*  __restrict__ x_id,
                const float*  __restrict__ a,
                const float*  __restrict__ b,
                const float4* __restrict__ pi4,
                const float4* __restrict__ mu4,
                const float4* __restrict__ s4,
                float* __restrict__ out,       // [N_ELEM]
                float* __restrict__ out_id,    // [N_ELEM]
                float* __restrict__ sldj_out)  // [BATCH]
{
    const int tid  = threadIdx.x;
    const int lane = tid & 31;

    int tile  = blockIdx.x;          // GRID(592) < NTILE(8192): always valid
    int stage = 0;

    // ---- prologue: stage tile0 + scalar pipeline regs ----
    prefetch_tile(0, tile, tid, pi4, mu4, s4);
    cp_commit();
    float xc  = __ldcs(&x_change[tile * TILE + tid]);
    float av  = __ldcs(&a[tile * TILE + tid]);
    float bv  = __ldcs(&b[tile * TILE + tid]);
    float xid = __ldcs(&x_id[tile * TILE + tid]);

    for (;;) {
        const int  tile_next = tile + GRID;
        const bool has_next  = (tile_next < NTILE);

        float xn = 0.f, an = 0.f, bn = 0.f, idn = 0.f;
        if (has_next) {
            prefetch_tile(stage ^ 1, tile_next, tid, pi4, mu4, s4);
            cp_commit();
            xn  = __ldcs(&x_change[tile_next * TILE + tid]);
            an  = __ldcs(&a[tile_next * TILE + tid]);
            bn  = __ldcs(&b[tile_next * TILE + tid]);
            idn = __ldcs(&x_id[tile_next * TILE + tid]);
            cp_wait1();                 // current tile's group complete
        } else {
            cp_wait0();
        }
        __syncthreads();                // stage data visible to all threads

        // ---- compute from smem (linear-domain mixture, see R2 derivation) ----
        const float4* __restrict__ sp = sm_stage[stage][0];
        const float4* __restrict__ smu = sm_stage[stage][1];
        const float4* __restrict__ ss  = sm_stage[stage][2];

        float S1 = 0.0f, S0 = 0.0f, P = 0.0f;
#pragma unroll
        for (int j = 0; j < 4; j++) {
            const float4 p4 = sp [tid * 4 + j];
            const float4 m4 = smu[tid * 4 + j];
            const float4 t4 = ss [tid * 4 + j];

            const float pk[4] = {p4.x, p4.y, p4.z, p4.w};
            const float mk[4] = {m4.x, m4.y, m4.z, m4.w};
            const float sk[4] = {t4.x, t4.y, t4.z, t4.w};
#pragma unroll
            for (int q = 0; q < 4; q++) {
                const float ep = __expf(pk[q]);
                const float es = __expf(-sk[q]);
                const float z  = (xc - mk[q]) * es;
                const float t  = __expf(-z);
                const float rc = __fdividef(1.0f, 1.0f + t);
                const float r1 = ep * rc;
                const float rt = r1 * t;
                S1 += r1;
                S0 += rt;
                P  += rt * (es * rc);
            }
        }

        const float lS1 = __logf(S1);
        const float lS0 = __logf(S0);
        const float lSe = __logf(S1 + S0);
        const float lP  = __logf(P);

        const int i = tile * TILE + tid;
        __stcs(&out[i],    (lS1 - lS0 + bv) * __expf(av));
        __stcs(&out_id[i], xid);

        // ---- warp-level ldj reduction, one atomic per warp ----
        float v = lP + lSe - lS1 - lS0 + av;
#pragma unroll
        for (int off = 16; off > 0; off >>= 1)
            v += __shfl_down_sync(0xFFFFFFFFu, v, off);
        if (lane == 0)
            atomicAdd(&sldj_out[tile >> 8], v);   // 256 tiles per batch

        __syncthreads();                // all reads of this stage done before reuse
        if (!has_next) break;
        tile  = tile_next;
        stage ^= 1;
        xc = xn; av = an; bv = bn; xid = idn;
    }
}

extern "C" void kernel_launch(void* const* d_in, const int* in_sizes, int n_in,
                              void* d_out, int out_size) {
    // Inputs (metadata order): x_change, x_id, sldj, a, b, pi, mu, s
    const float* x_change = (const float*)d_in[0];
    const float* x_id     = (const float*)d_in[1];
    const float* sldj     = (const float*)d_in[2];
    const float* a        = (const float*)d_in[3];
    const float* b        = (const float*)d_in[4];
    const float4* pi4     = (const float4*)d_in[5];
    const float4* mu4     = (const float4*)d_in[6];
    const float4* s4      = (const float4*)d_in[7];

    float* out      = (float*)d_out;
    float* out_id   = out + N_ELEM;
    float* sldj_out = out + 2 * N_ELEM;

    init_sldj_kernel<<<1, 32>>>(sldj, sldj_out);
    coupling_kernel<<<GRID, TPB>>>(x_change, x_id, a, b,
                                   pi4, mu4, s4,
                                   out, out_id, sldj_out);
}